// round 3
// baseline (speedup 1.0000x reference)
#include <cuda_runtime.h>
#include <math.h>

#define NMAX 100000
#define EMAX 600000
#define IN_F 128
#define OUT_F 64

// Scratch (static device globals — allocation-free per harness rules)
__device__ float g_Wsn[IN_F * OUT_F];
__device__ float g_xp[(size_t)NMAX * OUT_F];
__device__ float g_deg[NMAX];
__device__ float g_dis[NMAX];
__device__ float g_w[EMAX];
__device__ float g_coef[EMAX];
__device__ int   g_is64;   // 1 if edge_index is int64 on device, 0 if int32

// ---------------------------------------------------------------------------
// 0) Detect edge_index dtype. For int64 indices < 2^31 (little-endian), every
//    odd 32-bit word is zero. For int32 data, odd words are random indices.
// ---------------------------------------------------------------------------
__global__ void k_detect(const unsigned int* __restrict__ p, int nwords) {
    __shared__ int any;
    if (threadIdx.x == 0) any = 0;
    __syncthreads();
    int limit = nwords < 8192 ? nwords : 8192;
    for (int i = 1 + 2 * threadIdx.x; i < limit; i += 2 * blockDim.x)
        if (p[i] != 0u) any = 1;
    __syncthreads();
    if (threadIdx.x == 0) g_is64 = (any == 0) ? 1 : 0;
}

__device__ __forceinline__ long long load_idx(const void* ei, size_t pos, int is64) {
    if (is64) return ((const long long*)ei)[pos];
    return (long long)(((const int*)ei)[pos]);
}

// ---------------------------------------------------------------------------
// 1) Spectral norm: v = l2norm(W^T u); sigma = ||Wv||^2 / (||Wv||+eps);
//    W_sn = W / sigma.  One block, 128 threads.
// ---------------------------------------------------------------------------
__global__ void k_spectral(const float* __restrict__ W, const float* __restrict__ u) {
    __shared__ float su[IN_F];
    __shared__ float sv[OUT_F];
    __shared__ float red[IN_F];
    int t = threadIdx.x;

    su[t] = u[t];
    __syncthreads();

    // t_j = sum_i W[i,j] * u[i]   (threads 0..63)
    float tj = 0.f;
    if (t < OUT_F) {
        #pragma unroll 8
        for (int i = 0; i < IN_F; i++) tj += W[i * OUT_F + t] * su[i];
    }
    red[t] = (t < OUT_F) ? tj * tj : 0.f;
    __syncthreads();
    for (int s = 64; s > 0; s >>= 1) {
        if (t < s) red[t] += red[t + s];
        __syncthreads();
    }
    float tn = sqrtf(red[0]) + 1e-12f;
    __syncthreads();
    if (t < OUT_F) sv[t] = tj / tn;
    __syncthreads();

    // Wv_i = sum_j W[i,j] * v[j]   (all 128 threads)
    float wv = 0.f;
    #pragma unroll 8
    for (int j = 0; j < OUT_F; j++) wv += W[t * OUT_F + j] * sv[j];
    red[t] = wv * wv;
    __syncthreads();
    for (int s = 64; s > 0; s >>= 1) {
        if (t < s) red[t] += red[t + s];
        __syncthreads();
    }
    float s2 = red[0];
    float nrm = sqrtf(s2);
    float sigma = s2 / (nrm + 1e-12f);
    float inv = 1.0f / sigma;

    for (int idx = t; idx < IN_F * OUT_F; idx += 128) g_Wsn[idx] = W[idx] * inv;
}

// ---------------------------------------------------------------------------
// 2) Degree init (self-loop contributes 1.0)
// ---------------------------------------------------------------------------
__global__ void k_deg_init(int N) {
    int i = blockIdx.x * blockDim.x + threadIdx.x;
    if (i < N) g_deg[i] = 1.0f;
}

// 3) deg[col] += sigmoid(ew[e]); stash sigmoid
__global__ void k_deg(const void* __restrict__ ei, const float* __restrict__ ew, int E) {
    int e = blockIdx.x * blockDim.x + threadIdx.x;
    if (e >= E) return;
    int is64 = g_is64;
    float w = 1.0f / (1.0f + expf(-ew[e]));
    g_w[e] = w;
    long long c = load_idx(ei, (size_t)E + e, is64);
    atomicAdd(&g_deg[c], w);
}

// 4) dis = rsqrt(deg)
__global__ void k_dis(int N) {
    int i = blockIdx.x * blockDim.x + threadIdx.x;
    if (i < N) g_dis[i] = rsqrtf(g_deg[i]);
}

// ---------------------------------------------------------------------------
// 5) GEMM: xp = x @ W_sn ; out = xp * (1/deg) + bias ; stash xp.
//    128 rows per block, 1 row per thread, full 64-col accumulator in regs.
// ---------------------------------------------------------------------------
#define BK 32
__global__ void __launch_bounds__(128) k_gemm(const float* __restrict__ x,
                                              const float* __restrict__ bias,
                                              float* __restrict__ out, int N) {
    __shared__ float  xs[128][BK + 1];
    __shared__ float4 ws[BK * 16];  // W chunk: [BK][64] as float4

    int t = threadIdx.x;
    int row0 = blockIdx.x * 128;
    int row = row0 + t;

    float4 acc[16];
    #pragma unroll
    for (int j = 0; j < 16; j++) acc[j] = make_float4(0.f, 0.f, 0.f, 0.f);

    for (int kc = 0; kc < IN_F; kc += BK) {
        // Load W chunk (BK*16 float4 = 512; 4 per thread)
        #pragma unroll
        for (int i = 0; i < 4; i++) {
            int idx = t + i * 128;
            ws[idx] = reinterpret_cast<const float4*>(g_Wsn)[kc * 16 + idx];
        }
        // Load x tile 128 rows x BK (coalesced; 32 per thread)
        #pragma unroll
        for (int i = 0; i < 32; i++) {
            int idx = t + i * 128;
            int r = idx / BK;
            int kk = idx % BK;
            float v = (row0 + r < N) ? x[(size_t)(row0 + r) * IN_F + kc + kk] : 0.f;
            xs[r][kk] = v;
        }
        __syncthreads();
        #pragma unroll 4
        for (int kk = 0; kk < BK; kk++) {
            float xv = xs[t][kk];
            #pragma unroll
            for (int j = 0; j < 16; j++) {
                float4 w = ws[kk * 16 + j];
                acc[j].x += xv * w.x;
                acc[j].y += xv * w.y;
                acc[j].z += xv * w.z;
                acc[j].w += xv * w.w;
            }
        }
        __syncthreads();
    }

    if (row < N) {
        float invd = 1.0f / g_deg[row];
        float4* xpp = reinterpret_cast<float4*>(&g_xp[(size_t)row * OUT_F]);
        float4* op = reinterpret_cast<float4*>(&out[(size_t)row * OUT_F]);
        const float4* b4 = reinterpret_cast<const float4*>(bias);
        #pragma unroll
        for (int j = 0; j < 16; j++) {
            xpp[j] = acc[j];
            float4 bb = b4[j];
            float4 o;
            o.x = acc[j].x * invd + bb.x;
            o.y = acc[j].y * invd + bb.y;
            o.z = acc[j].z * invd + bb.z;
            o.w = acc[j].w * invd + bb.w;
            op[j] = o;
        }
    }
}

// ---------------------------------------------------------------------------
// 6) Per-edge coefficient: coef = dis[row] * sigmoid(ew) * dis[col]
// ---------------------------------------------------------------------------
__global__ void k_coef(const void* __restrict__ ei, int E) {
    int e = blockIdx.x * blockDim.x + threadIdx.x;
    if (e >= E) return;
    int is64 = g_is64;
    long long r = load_idx(ei, (size_t)e, is64);
    long long c = load_idx(ei, (size_t)E + e, is64);
    g_coef[e] = g_dis[r] * g_w[e] * g_dis[c];
}

// ---------------------------------------------------------------------------
// 7) Scatter: out[col] += xp[row] * coef  (16 lanes/edge, float4 + red.v4)
// ---------------------------------------------------------------------------
__global__ void k_scatter(const void* __restrict__ ei, float* __restrict__ out, int E) {
    int gid = blockIdx.x * blockDim.x + threadIdx.x;
    int e = gid >> 4;
    if (e >= E) return;
    int lane = gid & 15;
    int is64 = g_is64;
    long long r = load_idx(ei, (size_t)e, is64);
    long long c = load_idx(ei, (size_t)E + e, is64);
    float ne = g_coef[e];
    float4 v = *reinterpret_cast<const float4*>(&g_xp[(size_t)r * OUT_F + lane * 4]);
    float* dst = &out[(size_t)c * OUT_F + lane * 4];
    asm volatile("red.global.add.v4.f32 [%0], {%1, %2, %3, %4};"
                 :: "l"(dst), "f"(v.x * ne), "f"(v.y * ne), "f"(v.z * ne), "f"(v.w * ne)
                 : "memory");
}

// ---------------------------------------------------------------------------
// Launch
// ---------------------------------------------------------------------------
extern "C" void kernel_launch(void* const* d_in, const int* in_sizes, int n_in,
                              void* d_out, int out_size) {
    const float* x    = (const float*)d_in[0];
    const void*  ei   = d_in[1];
    const float* W    = (const float*)d_in[2];
    const float* bias = (const float*)d_in[3];
    const float* ew   = (const float*)d_in[4];
    const float* u    = (const float*)d_in[5];
    float*       out  = (float*)d_out;

    int N = in_sizes[0] / IN_F;
    int E = in_sizes[4];
    if (N > NMAX) N = NMAX;
    if (E > EMAX) E = EMAX;

    k_detect<<<1, 256>>>((const unsigned int*)ei, 2 * E);
    k_spectral<<<1, 128>>>(W, u);
    k_deg_init<<<(N + 255) / 256, 256>>>(N);
    k_deg<<<(E + 255) / 256, 256>>>(ei, ew, E);
    k_dis<<<(N + 255) / 256, 256>>>(N);
    k_gemm<<<(N + 127) / 128, 128>>>(x, bias, out, N);
    k_coef<<<(E + 255) / 256, 256>>>(ei, E);
    k_scatter<<<((E * 16) + 255) / 256, 256>>>(ei, out, E);
}